// round 14
// baseline (speedup 1.0000x reference)
#include <cuda_runtime.h>
#include <cuda_fp16.h>
#include <cstdint>

// Problem constants (fixed by the reference)
#define BATCH  8
#define NNODE  20000
#define CDIM   256
#define NEDGE  320000

// ---------------- device scratch (allocation-free rule: __device__ globals) ---------
__device__ int   g_hi_nonzero;          // 1 => edge_index buffer is int32
__device__ int   g_deg[NNODE];
__device__ int   g_cnt[NNODE];
__device__ int   g_cursor[NNODE];
__device__ float g_dis[NNODE];
__device__ int   g_rowptr[NNODE + 1];
__device__ int   g_csr_src[NEDGE];
__device__ float g_csr_w[NEDGE];
__device__ __half g_feats16[(size_t)BATCH * NNODE * CDIM]; // 81.9 MB (A seg0 + gather)
__device__ __half g_Tx116  [(size_t)BATCH * NNODE * CDIM]; // 81.9 MB (A seg1 + gather)
// folded layer-1 weights, fp16, [K=768][N=256] row-major
__device__ __half g_W16[768 * 256];

// ---------------- dtype detection ---------------------------------------------------
// Node indices < 20000 -> int64 storage has zero high words everywhere.
__global__ void k_detect(const int* __restrict__ p32) {
    int t = threadIdx.x;
    if (p32[2 * t + 1] != 0) atomicOr(&g_hi_nonzero, 1);
}
__device__ __forceinline__ void load_edge(const int* __restrict__ p, int e, int& s, int& d) {
    if (g_hi_nonzero) { s = p[e];      d = p[NEDGE + e]; }
    else              { s = p[2 * e];  d = p[2 * (NEDGE + e)]; }
}

// ---------------- graph prep kernels ------------------------------------------------
__global__ void k_zero() {
    int i = blockIdx.x * blockDim.x + threadIdx.x;
    if (i < NNODE) { g_deg[i] = 0; g_cnt[i] = 0; g_cursor[i] = 0; }
    if (i == 0) g_hi_nonzero = 0;
}
__global__ void k_deg(const int* __restrict__ ei) {
    int e = blockIdx.x * blockDim.x + threadIdx.x;
    if (e < NEDGE) {
        int s, d; load_edge(ei, e, s, d);
        atomicAdd(&g_deg[s], 1);
        atomicAdd(&g_cnt[d], 1);
    }
}
__global__ void k_dis() {
    int i = blockIdx.x * blockDim.x + threadIdx.x;
    if (i < NNODE) {
        int d = g_deg[i];
        g_dis[i] = (d > 0) ? rsqrtf((float)d) : 0.0f;
    }
}
__global__ void k_scan() {
    __shared__ int sh[1024];
    const int CH = 20;
    int t = threadIdx.x;
    int base = t * CH;
    int sum = 0;
    for (int i = 0; i < CH; i++) { int idx = base + i; if (idx < NNODE) sum += g_cnt[idx]; }
    sh[t] = sum;
    __syncthreads();
    for (int o = 1; o < 1024; o <<= 1) {
        int v = (t >= o) ? sh[t - o] : 0;
        __syncthreads();
        sh[t] += v;
        __syncthreads();
    }
    int run = sh[t] - sum;
    for (int i = 0; i < CH; i++) {
        int idx = base + i;
        if (idx < NNODE) { g_rowptr[idx] = run; run += g_cnt[idx]; }
    }
    if (t == 1023) g_rowptr[NNODE] = sh[1023];
}
__global__ void k_fill(const int* __restrict__ ei) {
    int e = blockIdx.x * blockDim.x + threadIdx.x;
    if (e < NEDGE) {
        int s, d; load_edge(ei, e, s, d);
        float w = -g_dis[s] * g_dis[d];
        int pos = atomicAdd(&g_cursor[d], 1);
        int idx = g_rowptr[d] + pos;
        g_csr_src[idx] = s;
        g_csr_w[idx]   = w;
    }
}

// convert feats fp32 -> fp16 plane
__global__ void k_half(const float* __restrict__ f) {
    size_t i = (size_t)blockIdx.x * blockDim.x + threadIdx.x;   // over elems/4
    float4 x = ((const float4*)f)[i];
    __half2 a = __floats2half2_rn(x.x, x.y);
    __half2 b = __floats2half2_rn(x.z, x.w);
    uint2 p;
    p.x = *(uint32_t*)&a;
    p.y = *(uint32_t*)&b;
    ((uint2*)g_feats16)[i] = p;
}

// fold layer-1 weights into fp16, [K=768][N=256]:
// Wc = [W0-W2 ; W1 ; 2*W2]  (since Tx2 = 2*P2 - Tx0)
__global__ void k_wc(const float* __restrict__ W) {
    int idx = blockIdx.x * blockDim.x + threadIdx.x;   // < 3*256*256, = kg*256 + n
    const int CC = CDIM * CDIM;
    int seg = idx / CC;
    int r   = idx - seg * CC;
    const float* Wl = W + 1 * 3 * CC;  // layer 1
    float v;
    if      (seg == 0) v = Wl[r] - Wl[2 * CC + r];
    else if (seg == 1) v = Wl[CC + r];
    else               v = 2.0f * Wl[2 * CC + r];
    g_W16[idx] = __float2half_rn(v);
}

// ---------------- propagation phase 0: Tx1 = A_hat @ feats --------------------------
// Warp-per-node, barrier-free, fp16 in/out with fp32 accumulate.
__global__ void __launch_bounds__(256, 8)
k_prop0() {
    int wid  = threadIdx.x >> 5;
    int lane = threadIdx.x & 31;
    int v    = blockIdx.x * 8 + wid;
    int b    = blockIdx.y;

    int start = g_rowptr[v];
    int end   = g_rowptr[v + 1];

    const uint4* X = (const uint4*)(g_feats16 + (size_t)b * NNODE * CDIM);

    float acc[8];
    #pragma unroll
    for (int j = 0; j < 8; j++) acc[j] = 0.0f;

    #pragma unroll 4
    for (int e = start; e < end; e++) {
        int   s = __ldg(&g_csr_src[e]);
        float w = __ldg(&g_csr_w[e]);
        uint4 raw = X[(size_t)s * 32 + lane];
        float2 f0 = __half22float2(*(__half2*)&raw.x);
        float2 f1 = __half22float2(*(__half2*)&raw.y);
        float2 f2 = __half22float2(*(__half2*)&raw.z);
        float2 f3 = __half22float2(*(__half2*)&raw.w);
        acc[0] += w * f0.x; acc[1] += w * f0.y;
        acc[2] += w * f1.x; acc[3] += w * f1.y;
        acc[4] += w * f2.x; acc[5] += w * f2.y;
        acc[6] += w * f3.x; acc[7] += w * f3.y;
    }

    __half2 o0 = __floats2half2_rn(acc[0], acc[1]);
    __half2 o1 = __floats2half2_rn(acc[2], acc[3]);
    __half2 o2 = __floats2half2_rn(acc[4], acc[5]);
    __half2 o3 = __floats2half2_rn(acc[6], acc[7]);
    uint4 p;
    p.x = *(uint32_t*)&o0; p.y = *(uint32_t*)&o1;
    p.z = *(uint32_t*)&o2; p.w = *(uint32_t*)&o3;
    ((uint4*)(g_Tx116 + (size_t)b * NNODE * CDIM))[(size_t)v * 32 + lane] = p;
}

// ---------------- mma.sync helpers ----------------------------------------------------
__device__ __forceinline__ uint32_t smem_u32(const void* p) {
    uint32_t a;
    asm("{ .reg .u64 t; cvta.to.shared.u64 t, %1; cvt.u32.u64 %0, t; }" : "=r"(a) : "l"(p));
    return a;
}
__device__ __forceinline__ void ldsm_x4(uint32_t& r0, uint32_t& r1, uint32_t& r2, uint32_t& r3,
                                        uint32_t addr) {
    asm volatile("ldmatrix.sync.aligned.m8n8.x4.shared.b16 {%0,%1,%2,%3}, [%4];"
                 : "=r"(r0), "=r"(r1), "=r"(r2), "=r"(r3) : "r"(addr));
}
__device__ __forceinline__ void ldsm_x2t(uint32_t& r0, uint32_t& r1, uint32_t addr) {
    asm volatile("ldmatrix.sync.aligned.m8n8.x2.trans.shared.b16 {%0,%1}, [%2];"
                 : "=r"(r0), "=r"(r1) : "r"(addr));
}
__device__ __forceinline__ void mma_f16(float* c, const uint32_t* a, uint32_t b0, uint32_t b1) {
    asm volatile("mma.sync.aligned.m16n8k16.row.col.f32.f16.f16.f32 "
                 "{%0,%1,%2,%3}, {%4,%5,%6,%7}, {%8,%9}, {%0,%1,%2,%3};"
                 : "+f"(c[0]), "+f"(c[1]), "+f"(c[2]), "+f"(c[3])
                 : "r"(a[0]), "r"(a[1]), "r"(a[2]), "r"(a[3]), "r"(b0), "r"(b1));
}
__device__ __forceinline__ void cp16(uint32_t dst, const void* src) {
    asm volatile("{ .reg .u64 g; cvta.to.global.u64 g, %1;\n\t"
                 "cp.async.ca.shared.global [%0], [g], 16; }" :: "r"(dst), "l"(src));
}

// ---------------- fused GEMM + INTERLEAVED in-CTA P2 gather + bias + LN --------------
// out[160000,256] = [Tx0|Tx1|P2](M x 768) @ W16 + b, then row LN.
// P2 rows gathered from g_Tx116 INSIDE the MMA chunk loop: warp wid computes its row
// r at chunk c=2r (chunks 0..15), so gather latency hides under other warps' HMMAs.
// Chunks 16..23 ldmatrix A directly from the SMEM P2 buffer.
// CTA: M=64, N=256, BK=32. 8 warps = 2(M) x 4(N); warp tile 32 x 64.
#define A_ROWB  80                     // 32 fp16 = 64B + 16B pad
#define A_STG   (64 * A_ROWB)          // 5120
#define B_ROWB  528                    // 256 fp16 = 512B + 16B pad
#define B_STG   (32 * B_ROWB)          // 16896
#define OFF_A(s) ((s) * A_STG)                 // 0 / 5120
#define OFF_B(s) (2 * A_STG + (s) * B_STG)     // 10240 / 27136
#define P2OFF   (2 * A_STG + 2 * B_STG)        // 44032
#define P2_ROWB 528
#define SMEM_DYN (P2OFF + 64 * P2_ROWB)        // 77824 (>= 64KB epilogue alias)

__global__ void __launch_bounds__(256, 2)
k_gemm_mma(const float* __restrict__ bias,
           const float* __restrict__ lnw,
           const float* __restrict__ lnb,
           float* __restrict__ out)
{
    extern __shared__ char smem[];
    const uint32_t sb = smem_u32(smem);
    const int tid  = threadIdx.x;
    const int wid  = tid >> 5;
    const int lane = tid & 31;
    const int wm   = wid >> 2;          // 0..1 (M)
    const int wn   = wid & 3;           // 0..3 (N)
    const int m0   = blockIdx.x * 64;

    // A: 256 x 16B chunks cover [64][32] fp16; thread t -> row=t>>2, q=t&3
    const int arow = tid >> 2;
    const int aq   = tid & 3;

    // prefetch helper: A chunk (seg0/seg1 only) + B chunk -> one cp.async group
    auto prefetch = [&](int c, int s) {
        if (c < 16) {
            const __half* Aseg = (c < 8) ? g_feats16 : g_Tx116;
            int koff = (c & 7) * 32;
            cp16(sb + OFF_A(s) + arow * A_ROWB + aq * 16,
                 Aseg + (size_t)(m0 + arow) * CDIM + koff + aq * 8);
        }
        int kb = c * 32;
        #pragma unroll
        for (int i = 0; i < 4; i++) {
            int idx = tid + 256 * i;       // 0..1023
            int row = idx >> 5;            // 0..31
            int q   = idx & 31;            // 16B chunk in 512B row
            cp16(sb + OFF_B(s) + row * B_ROWB + q * 16,
                 g_W16 + (size_t)(kb + row) * 256 + q * 8);
        }
        asm volatile("cp.async.commit_group;" ::: "memory");
    };

    prefetch(0, 0);

    float acc[2][8][4];
    #pragma unroll
    for (int mt = 0; mt < 2; mt++)
        #pragma unroll
        for (int nt = 0; nt < 8; nt++)
            #pragma unroll
            for (int q = 0; q < 4; q++) acc[mt][nt][q] = 0.0f;

    for (int c = 0; c < 24; c++) {
        const int s = c & 1;

        __syncthreads();                   // reads of stage s^1 (prev compute) done
        if (c + 1 < 24) {
            prefetch(c + 1, s ^ 1);
            asm volatile("cp.async.wait_group 1;" ::: "memory");   // chunk c ready
        } else {
            asm volatile("cp.async.wait_group 0;" ::: "memory");
        }
        __syncthreads();                   // stage s visible to all

        // ---- interleaved P2 gather: warp wid does its row (c>>1) at even chunks ----
        // Gather loads overlap other warps' (and this warp's later) HMMA issue.
        if (c < 16 && (c & 1) == 0) {
            int r    = c >> 1;                 // 0..7
            int rowl = wid * 8 + r;            // local row in [0,64)
            int row  = m0 + rowl;
            int b    = row / NNODE;
            int v    = row - b * NNODE;
            int start = g_rowptr[v];
            int end   = g_rowptr[v + 1];
            const uint4* X = (const uint4*)(g_Tx116 + (size_t)b * NNODE * CDIM);

            float a0 = 0.f, a1 = 0.f, a2 = 0.f, a3 = 0.f,
                  a4 = 0.f, a5 = 0.f, a6 = 0.f, a7 = 0.f;
            #pragma unroll 4
            for (int e = start; e < end; e++) {
                int   sidx = __ldg(&g_csr_src[e]);
                float w    = __ldg(&g_csr_w[e]);
                uint4 raw = X[(size_t)sidx * 32 + lane];
                float2 f0 = __half22float2(*(__half2*)&raw.x);
                float2 f1 = __half22float2(*(__half2*)&raw.y);
                float2 f2 = __half22float2(*(__half2*)&raw.z);
                float2 f3 = __half22float2(*(__half2*)&raw.w);
                a0 += w * f0.x; a1 += w * f0.y;
                a2 += w * f1.x; a3 += w * f1.y;
                a4 += w * f2.x; a5 += w * f2.y;
                a6 += w * f3.x; a7 += w * f3.y;
            }
            __half2 o0 = __floats2half2_rn(a0, a1);
            __half2 o1 = __floats2half2_rn(a2, a3);
            __half2 o2 = __floats2half2_rn(a4, a5);
            __half2 o3 = __floats2half2_rn(a6, a7);
            uint4 p;
            p.x = *(uint32_t*)&o0; p.y = *(uint32_t*)&o1;
            p.z = *(uint32_t*)&o2; p.w = *(uint32_t*)&o3;
            *(uint4*)(smem + P2OFF + rowl * P2_ROWB + lane * 16) = p;
        }

        // ---- mma over BK=32 (2 k-steps of 16) ----
        #pragma unroll
        for (int k = 0; k < 2; k++) {
            uint32_t af[2][4];
            #pragma unroll
            for (int mt = 0; mt < 2; mt++) {
                uint32_t ar = (uint32_t)(wm * 32 + mt * 16 + (lane & 15));
                uint32_t aoff;
                if (c < 16)
                    aoff = OFF_A(s) + ar * A_ROWB + (uint32_t)(k * 32 + (lane >> 4) * 16);
                else
                    aoff = P2OFF + ar * P2_ROWB
                         + (uint32_t)((c - 16) * 64 + k * 32 + (lane >> 4) * 16);
                ldsm_x4(af[mt][0], af[mt][1], af[mt][2], af[mt][3], sb + aoff);
            }
            #pragma unroll
            for (int nt = 0; nt < 8; nt++) {
                uint32_t boff = OFF_B(s) + (uint32_t)(k * 16 + (lane & 15)) * B_ROWB
                              + (uint32_t)(wn * 64 + nt * 8) * 2;
                uint32_t b0, b1;
                ldsm_x2t(b0, b1, sb + boff);
                #pragma unroll
                for (int mt = 0; mt < 2; mt++)
                    mma_f16(acc[mt][nt], af[mt], b0, b1);
            }
        }
    }

    // ---- epilogue: acc -> SMEM, then LN per row ----
    __syncthreads();
    float* ep = (float*)smem;                 // [64][256] f32 = 64KB (aliases all bufs)
    #pragma unroll
    for (int mt = 0; mt < 2; mt++) {
        int r0 = wm * 32 + mt * 16 + (lane >> 2);
        #pragma unroll
        for (int nt = 0; nt < 8; nt++) {
            int cbase = wn * 64 + nt * 8 + (lane & 3) * 2;
            *(float2*)(ep + r0 * 256 + cbase)       = make_float2(acc[mt][nt][0], acc[mt][nt][1]);
            *(float2*)(ep + (r0 + 8) * 256 + cbase) = make_float2(acc[mt][nt][2], acc[mt][nt][3]);
        }
    }
    __syncthreads();

    // warp wid handles rows wid*8..+8; lane covers cols {j*32+lane}
    float bb[8], lw[8], lb[8];
    #pragma unroll
    for (int j = 0; j < 8; j++) {
        int col = j * 32 + lane;
        bb[j] = bias[col]; lw[j] = lnw[col]; lb[j] = lnb[col];
    }
    #pragma unroll
    for (int i = 0; i < 8; i++) {
        int row = wid * 8 + i;
        float v[8];
        float ssum = 0.0f;
        #pragma unroll
        for (int j = 0; j < 8; j++) {
            v[j] = ep[row * 256 + j * 32 + lane] + bb[j];
            ssum += v[j];
        }
        #pragma unroll
        for (int o = 16; o > 0; o >>= 1) ssum += __shfl_xor_sync(0xffffffffu, ssum, o);
        float mu = ssum * (1.0f / CDIM);
        float s2 = 0.0f;
        #pragma unroll
        for (int j = 0; j < 8; j++) { float d = v[j] - mu; s2 += d * d; }
        #pragma unroll
        for (int o = 16; o > 0; o >>= 1) s2 += __shfl_xor_sync(0xffffffffu, s2, o);
        float inv = rsqrtf(s2 * (1.0f / CDIM) + 1e-5f);

        size_t rbase = ((size_t)m0 + row) * CDIM;
        #pragma unroll
        for (int j = 0; j < 8; j++)
            out[rbase + j * 32 + lane] = (v[j] - mu) * inv * lw[j] + lb[j];
    }
}

// ---------------- launch -------------------------------------------------------------
extern "C" void kernel_launch(void* const* d_in, const int* in_sizes, int n_in,
                              void* d_out, int out_size) {
    const float* feats = (const float*)d_in[0];      // [B*N, C]
    const float* W     = (const float*)d_in[1];      // [L,K,C,C]
    const float* bpar  = (const float*)d_in[2];      // [L,C]
    const float* lnw   = (const float*)d_in[3];      // [L,C]
    const float* lnb   = (const float*)d_in[4];      // [L,C]
    const int*   ei    = (const int*)d_in[5];        // [2,E] int32 OR int64 (detected)
    float* out = (float*)d_out;

    cudaFuncSetAttribute(k_gemm_mma, cudaFuncAttributeMaxDynamicSharedMemorySize, SMEM_DYN);

    k_zero  <<<(NNODE + 255) / 256, 256>>>();
    k_detect<<<1, 256>>>(ei);
    k_deg   <<<(NEDGE + 255) / 256, 256>>>(ei);
    k_dis   <<<(NNODE + 255) / 256, 256>>>();
    k_scan  <<<1, 1024>>>();
    k_fill  <<<(NEDGE + 255) / 256, 256>>>(ei);
    k_wc    <<<(3 * CDIM * CDIM) / 256, 256>>>(W);
    k_half  <<<(BATCH * NNODE * CDIM / 4) / 256, 256>>>(feats);

    k_prop0<<<dim3(NNODE / 8, BATCH), 256>>>();   // Tx1 = A_hat @ feats

    // fused: GEMM with interleaved P2 gather + bias + LayerNorm (layer-1 params)
    k_gemm_mma<<<(BATCH * NNODE) / 64, 256, SMEM_DYN>>>(
        bpar + CDIM, lnw + CDIM, lnb + CDIM, out);
}

// round 15
// speedup vs baseline: 1.1574x; 1.1574x over previous
#include <cuda_runtime.h>
#include <cuda_fp16.h>
#include <cstdint>

// Problem constants (fixed by the reference)
#define BATCH  8
#define NNODE  20000
#define CDIM   256
#define NEDGE  320000

// ---------------- device scratch (allocation-free rule: __device__ globals) ---------
__device__ int   g_hi_nonzero;          // 1 => edge_index buffer is int32
__device__ int   g_deg[NNODE];
__device__ int   g_cnt[NNODE];
__device__ int   g_cursor[NNODE];
__device__ float g_dis[NNODE];
__device__ int   g_rowptr[NNODE + 1];
__device__ int   g_csr_src[NEDGE];
__device__ float g_csr_w[NEDGE];
__device__ __half g_feats16[(size_t)BATCH * NNODE * CDIM]; // 81.9 MB (A seg0 + gather)
__device__ __half g_Tx116  [(size_t)BATCH * NNODE * CDIM]; // 81.9 MB (A seg1 + gather)
__device__ __half g_P216   [(size_t)BATCH * NNODE * CDIM]; // 81.9 MB (A seg2)
// folded layer-1 weights, fp16, [K=768][N=256] row-major
__device__ __half g_W16[768 * 256];

// ---------------- dtype detection ---------------------------------------------------
// Node indices < 20000 -> int64 storage has zero high words everywhere.
__global__ void k_detect(const int* __restrict__ p32) {
    int t = threadIdx.x;
    if (p32[2 * t + 1] != 0) atomicOr(&g_hi_nonzero, 1);
}
__device__ __forceinline__ void load_edge(const int* __restrict__ p, int e, int& s, int& d) {
    if (g_hi_nonzero) { s = p[e];      d = p[NEDGE + e]; }
    else              { s = p[2 * e];  d = p[2 * (NEDGE + e)]; }
}

// ---------------- graph prep kernels ------------------------------------------------
__global__ void k_zero() {
    int i = blockIdx.x * blockDim.x + threadIdx.x;
    if (i < NNODE) { g_deg[i] = 0; g_cnt[i] = 0; g_cursor[i] = 0; }
    if (i == 0) g_hi_nonzero = 0;
}
__global__ void k_deg(const int* __restrict__ ei) {
    int e = blockIdx.x * blockDim.x + threadIdx.x;
    if (e < NEDGE) {
        int s, d; load_edge(ei, e, s, d);
        atomicAdd(&g_deg[s], 1);
        atomicAdd(&g_cnt[d], 1);
    }
}
__global__ void k_dis() {
    int i = blockIdx.x * blockDim.x + threadIdx.x;
    if (i < NNODE) {
        int d = g_deg[i];
        g_dis[i] = (d > 0) ? rsqrtf((float)d) : 0.0f;
    }
}
__global__ void k_scan() {
    __shared__ int sh[1024];
    const int CH = 20;
    int t = threadIdx.x;
    int base = t * CH;
    int sum = 0;
    for (int i = 0; i < CH; i++) { int idx = base + i; if (idx < NNODE) sum += g_cnt[idx]; }
    sh[t] = sum;
    __syncthreads();
    for (int o = 1; o < 1024; o <<= 1) {
        int v = (t >= o) ? sh[t - o] : 0;
        __syncthreads();
        sh[t] += v;
        __syncthreads();
    }
    int run = sh[t] - sum;
    for (int i = 0; i < CH; i++) {
        int idx = base + i;
        if (idx < NNODE) { g_rowptr[idx] = run; run += g_cnt[idx]; }
    }
    if (t == 1023) g_rowptr[NNODE] = sh[1023];
}
__global__ void k_fill(const int* __restrict__ ei) {
    int e = blockIdx.x * blockDim.x + threadIdx.x;
    if (e < NEDGE) {
        int s, d; load_edge(ei, e, s, d);
        float w = -g_dis[s] * g_dis[d];
        int pos = atomicAdd(&g_cursor[d], 1);
        int idx = g_rowptr[d] + pos;
        g_csr_src[idx] = s;
        g_csr_w[idx]   = w;
    }
}

// convert feats fp32 -> fp16 plane
__global__ void k_half(const float* __restrict__ f) {
    size_t i = (size_t)blockIdx.x * blockDim.x + threadIdx.x;   // over elems/4
    float4 x = ((const float4*)f)[i];
    __half2 a = __floats2half2_rn(x.x, x.y);
    __half2 b = __floats2half2_rn(x.z, x.w);
    uint2 p;
    p.x = *(uint32_t*)&a;
    p.y = *(uint32_t*)&b;
    ((uint2*)g_feats16)[i] = p;
}

// fold layer-1 weights into fp16, [K=768][N=256]:
// Wc = [W0-W2 ; W1 ; 2*W2]  (since Tx2 = 2*P2 - Tx0)
__global__ void k_wc(const float* __restrict__ W) {
    int idx = blockIdx.x * blockDim.x + threadIdx.x;   // < 3*256*256, = kg*256 + n
    const int CC = CDIM * CDIM;
    int seg = idx / CC;
    int r   = idx - seg * CC;
    const float* Wl = W + 1 * 3 * CC;  // layer 1
    float v;
    if      (seg == 0) v = Wl[r] - Wl[2 * CC + r];
    else if (seg == 1) v = Wl[CC + r];
    else               v = 2.0f * Wl[2 * CC + r];
    g_W16[idx] = __float2half_rn(v);
}

// ---------------- propagation: Y[b,v,:] = sum_e norm[e] * X[b,src[e],:] ------------
// Warp-per-node, barrier-free, fp16 in/out with fp32 accumulate.
// phase 0: g_feats16 -> g_Tx116.  phase 1: g_Tx116 -> g_P216.
__global__ void __launch_bounds__(256, 8)
k_prop(int phase) {
    const __half* X16 = (phase == 0) ? g_feats16 : g_Tx116;
    __half*       Y16 = (phase == 0) ? g_Tx116 : g_P216;

    int wid  = threadIdx.x >> 5;
    int lane = threadIdx.x & 31;
    int v    = blockIdx.x * 8 + wid;
    int b    = blockIdx.y;

    int start = g_rowptr[v];
    int end   = g_rowptr[v + 1];

    const uint4* X = (const uint4*)(X16 + (size_t)b * NNODE * CDIM);

    float acc[8];
    #pragma unroll
    for (int j = 0; j < 8; j++) acc[j] = 0.0f;

    #pragma unroll 4
    for (int e = start; e < end; e++) {
        int   s = __ldg(&g_csr_src[e]);
        float w = __ldg(&g_csr_w[e]);
        uint4 raw = X[(size_t)s * 32 + lane];
        float2 f0 = __half22float2(*(__half2*)&raw.x);
        float2 f1 = __half22float2(*(__half2*)&raw.y);
        float2 f2 = __half22float2(*(__half2*)&raw.z);
        float2 f3 = __half22float2(*(__half2*)&raw.w);
        acc[0] += w * f0.x; acc[1] += w * f0.y;
        acc[2] += w * f1.x; acc[3] += w * f1.y;
        acc[4] += w * f2.x; acc[5] += w * f2.y;
        acc[6] += w * f3.x; acc[7] += w * f3.y;
    }

    __half2 o0 = __floats2half2_rn(acc[0], acc[1]);
    __half2 o1 = __floats2half2_rn(acc[2], acc[3]);
    __half2 o2 = __floats2half2_rn(acc[4], acc[5]);
    __half2 o3 = __floats2half2_rn(acc[6], acc[7]);
    uint4 p;
    p.x = *(uint32_t*)&o0; p.y = *(uint32_t*)&o1;
    p.z = *(uint32_t*)&o2; p.w = *(uint32_t*)&o3;
    ((uint4*)(Y16 + (size_t)b * NNODE * CDIM))[(size_t)v * 32 + lane] = p;
}

// ---------------- mma.sync helpers ----------------------------------------------------
__device__ __forceinline__ uint32_t smem_u32(const void* p) {
    uint32_t a;
    asm("{ .reg .u64 t; cvta.to.shared.u64 t, %1; cvt.u32.u64 %0, t; }" : "=r"(a) : "l"(p));
    return a;
}
__device__ __forceinline__ void ldsm_x4(uint32_t& r0, uint32_t& r1, uint32_t& r2, uint32_t& r3,
                                        uint32_t addr) {
    asm volatile("ldmatrix.sync.aligned.m8n8.x4.shared.b16 {%0,%1,%2,%3}, [%4];"
                 : "=r"(r0), "=r"(r1), "=r"(r2), "=r"(r3) : "r"(addr));
}
__device__ __forceinline__ void ldsm_x2t(uint32_t& r0, uint32_t& r1, uint32_t addr) {
    asm volatile("ldmatrix.sync.aligned.m8n8.x2.trans.shared.b16 {%0,%1}, [%2];"
                 : "=r"(r0), "=r"(r1) : "r"(addr));
}
__device__ __forceinline__ void mma_f16(float* c, const uint32_t* a, uint32_t b0, uint32_t b1) {
    asm volatile("mma.sync.aligned.m16n8k16.row.col.f32.f16.f16.f32 "
                 "{%0,%1,%2,%3}, {%4,%5,%6,%7}, {%8,%9}, {%0,%1,%2,%3};"
                 : "+f"(c[0]), "+f"(c[1]), "+f"(c[2]), "+f"(c[3])
                 : "r"(a[0]), "r"(a[1]), "r"(a[2]), "r"(a[3]), "r"(b0), "r"(b1));
}
__device__ __forceinline__ void cp16(uint32_t dst, const void* src) {
    asm volatile("{ .reg .u64 g; cvta.to.global.u64 g, %1;\n\t"
                 "cp.async.ca.shared.global [%0], [g], 16; }" :: "r"(dst), "l"(src));
}

// ---------------- GEMM (mma.sync fp16, BM=128) + bias + LayerNorm --------------------
// out[160000,256] = [Tx0|Tx1|P2]_fp16 (M x 768) @ W16 + b, then row LN.
// CTA: M=128, N=256, BK=32. 8 warps = 2(M) x 4(N); warp tile 64 x 64 (mt=4).
// Cuts LDSM-per-HMMA from 10/16 to 12/32 and halves per-CTA B traffic vs BM=64.
#define A_ROWB  80                     // 32 fp16 = 64B + 16B pad
#define A_STG   (128 * A_ROWB)         // 10240
#define B_ROWB  528                    // 256 fp16 = 512B + 16B pad
#define B_STG   (32 * B_ROWB)          // 16896
#define OFF_A(s) ((s) * A_STG)                 // 0 / 10240
#define OFF_B(s) (2 * A_STG + (s) * B_STG)     // 20480 / 37376
#define SMEM_DYN 65536                 // >= 54272 stages; fits [64][256] f32 epilogue

__global__ void __launch_bounds__(256, 1)
k_gemm_mma(const float* __restrict__ bias,
           const float* __restrict__ lnw,
           const float* __restrict__ lnb,
           float* __restrict__ out)
{
    extern __shared__ char smem[];
    const uint32_t sb = smem_u32(smem);
    const int tid  = threadIdx.x;
    const int wid  = tid >> 5;
    const int lane = tid & 31;
    const int wm   = wid >> 2;          // 0..1 (M): rows wm*64 .. +64
    const int wn   = wid & 3;           // 0..3 (N): cols wn*64 .. +64
    const int m0   = blockIdx.x * 128;

    // A: [128][32] fp16 = 512 x 16B chunks; thread t -> 2 chunks
    const int arow = tid >> 2;          // rows 0..63 (+64 on second chunk)
    const int aq   = tid & 3;

    // prefetch helper: A chunk + B chunk -> one cp.async group
    auto prefetch = [&](int c, int s) {
        int seg  = c >> 3;
        const __half* Aseg = (seg == 0) ? g_feats16 : (seg == 1) ? g_Tx116 : g_P216;
        int koff = (c & 7) * 32;
        #pragma unroll
        for (int i = 0; i < 2; i++) {
            int row = arow + i * 64;
            cp16(sb + OFF_A(s) + row * A_ROWB + aq * 16,
                 Aseg + (size_t)(m0 + row) * CDIM + koff + aq * 8);
        }
        int kb = c * 32;
        #pragma unroll
        for (int i = 0; i < 4; i++) {
            int idx = tid + 256 * i;       // 0..1023
            int row = idx >> 5;            // 0..31
            int q   = idx & 31;            // 16B chunk in 512B row
            cp16(sb + OFF_B(s) + row * B_ROWB + q * 16,
                 g_W16 + (size_t)(kb + row) * 256 + q * 8);
        }
        asm volatile("cp.async.commit_group;" ::: "memory");
    };

    prefetch(0, 0);

    float acc[4][8][4];
    #pragma unroll
    for (int mt = 0; mt < 4; mt++)
        #pragma unroll
        for (int nt = 0; nt < 8; nt++)
            #pragma unroll
            for (int q = 0; q < 4; q++) acc[mt][nt][q] = 0.0f;

    for (int c = 0; c < 24; c++) {
        const int s = c & 1;

        __syncthreads();                   // reads of stage s^1 (prev compute) done
        if (c + 1 < 24) {
            prefetch(c + 1, s ^ 1);
            asm volatile("cp.async.wait_group 1;" ::: "memory");   // chunk c ready
        } else {
            asm volatile("cp.async.wait_group 0;" ::: "memory");
        }
        __syncthreads();                   // stage s visible to all

        #pragma unroll
        for (int k = 0; k < 2; k++) {
            uint32_t af[4][4];
            #pragma unroll
            for (int mt = 0; mt < 4; mt++) {
                uint32_t ar = (uint32_t)(wm * 64 + mt * 16 + (lane & 15));
                uint32_t aoff = OFF_A(s) + ar * A_ROWB + (uint32_t)(k * 32 + (lane >> 4) * 16);
                ldsm_x4(af[mt][0], af[mt][1], af[mt][2], af[mt][3], sb + aoff);
            }
            #pragma unroll
            for (int nt = 0; nt < 8; nt++) {
                uint32_t boff = OFF_B(s) + (uint32_t)(k * 16 + (lane & 15)) * B_ROWB
                              + (uint32_t)(wn * 64 + nt * 8) * 2;
                uint32_t b0, b1;
                ldsm_x2t(b0, b1, sb + boff);
                #pragma unroll
                for (int mt = 0; mt < 4; mt++)
                    mma_f16(acc[mt][nt], af[mt], b0, b1);
            }
        }
    }

    // ---- epilogue: two 64-row passes through a [64][256] f32 SMEM buffer ----
    float* ep = (float*)smem;
    float bb[8], lw[8], lb[8];
    #pragma unroll
    for (int j = 0; j < 8; j++) {
        int col = j * 32 + lane;
        bb[j] = bias[col]; lw[j] = lnw[col]; lb[j] = lnb[col];
    }

    #pragma unroll
    for (int p = 0; p < 2; p++) {
        __syncthreads();                    // buffer free (stages dead / prev pass done)
        if (wm == p) {
            #pragma unroll
            for (int mt = 0; mt < 4; mt++) {
                int r0 = mt * 16 + (lane >> 2);     // local row in [0,64)
                #pragma unroll
                for (int nt = 0; nt < 8; nt++) {
                    int cbase = wn * 64 + nt * 8 + (lane & 3) * 2;
                    *(float2*)(ep + r0 * 256 + cbase) =
                        make_float2(acc[mt][nt][0], acc[mt][nt][1]);
                    *(float2*)(ep + (r0 + 8) * 256 + cbase) =
                        make_float2(acc[mt][nt][2], acc[mt][nt][3]);
                }
            }
        }
        __syncthreads();

        // LN: warp wid handles local rows wid*8..+8; lane covers cols {j*32+lane}
        #pragma unroll
        for (int i = 0; i < 8; i++) {
            int row = wid * 8 + i;
            float v[8];
            float ssum = 0.0f;
            #pragma unroll
            for (int j = 0; j < 8; j++) {
                v[j] = ep[row * 256 + j * 32 + lane] + bb[j];
                ssum += v[j];
            }
            #pragma unroll
            for (int o = 16; o > 0; o >>= 1) ssum += __shfl_xor_sync(0xffffffffu, ssum, o);
            float mu = ssum * (1.0f / CDIM);
            float s2 = 0.0f;
            #pragma unroll
            for (int j = 0; j < 8; j++) { float d = v[j] - mu; s2 += d * d; }
            #pragma unroll
            for (int o = 16; o > 0; o >>= 1) s2 += __shfl_xor_sync(0xffffffffu, s2, o);
            float inv = rsqrtf(s2 * (1.0f / CDIM) + 1e-5f);

            size_t rbase = ((size_t)m0 + p * 64 + row) * CDIM;
            #pragma unroll
            for (int j = 0; j < 8; j++)
                out[rbase + j * 32 + lane] = (v[j] - mu) * inv * lw[j] + lb[j];
        }
    }
}

// ---------------- launch -------------------------------------------------------------
extern "C" void kernel_launch(void* const* d_in, const int* in_sizes, int n_in,
                              void* d_out, int out_size) {
    const float* feats = (const float*)d_in[0];      // [B*N, C]
    const float* W     = (const float*)d_in[1];      // [L,K,C,C]
    const float* bpar  = (const float*)d_in[2];      // [L,C]
    const float* lnw   = (const float*)d_in[3];      // [L,C]
    const float* lnb   = (const float*)d_in[4];      // [L,C]
    const int*   ei    = (const int*)d_in[5];        // [2,E] int32 OR int64 (detected)
    float* out = (float*)d_out;

    cudaFuncSetAttribute(k_gemm_mma, cudaFuncAttributeMaxDynamicSharedMemorySize, SMEM_DYN);

    k_zero  <<<(NNODE + 255) / 256, 256>>>();
    k_detect<<<1, 256>>>(ei);
    k_deg   <<<(NEDGE + 255) / 256, 256>>>(ei);
    k_dis   <<<(NNODE + 255) / 256, 256>>>();
    k_scan  <<<1, 1024>>>();
    k_fill  <<<(NEDGE + 255) / 256, 256>>>(ei);
    k_wc    <<<(3 * CDIM * CDIM) / 256, 256>>>(W);
    k_half  <<<(BATCH * NNODE * CDIM / 4) / 256, 256>>>(feats);

    k_prop<<<dim3(NNODE / 8, BATCH), 256>>>(0);   // Tx1 = A_hat @ feats
    k_prop<<<dim3(NNODE / 8, BATCH), 256>>>(1);   // P2  = A_hat @ Tx1

    // only layer 1 survives in the reference -> use its params
    k_gemm_mma<<<(BATCH * NNODE) / 128, 256, SMEM_DYN>>>(
        bpar + CDIM, lnw + CDIM, lnb + CDIM, out);
}

// round 16
// speedup vs baseline: 1.2404x; 1.0717x over previous
#include <cuda_runtime.h>
#include <cuda_fp16.h>
#include <cstdint>

// Problem constants (fixed by the reference)
#define BATCH  8
#define NNODE  20000
#define CDIM   256
#define NEDGE  320000

// ---------------- device scratch (allocation-free rule: __device__ globals) ---------
__device__ int   g_hi_nonzero;          // 1 => edge_index buffer is int32
__device__ int   g_deg[NNODE];
__device__ int   g_cnt[NNODE];
__device__ int   g_cursor[NNODE];
__device__ float g_dis[NNODE];
__device__ int   g_rowptr[NNODE + 1];
__device__ int   g_csr_src[NEDGE];
__device__ float g_csr_w[NEDGE];
__device__ __half g_feats16[(size_t)BATCH * NNODE * CDIM]; // 81.9 MB (A seg0 + gather)
__device__ __half g_Tx116  [(size_t)BATCH * NNODE * CDIM]; // 81.9 MB (A seg1 + gather)
__device__ __half g_P216   [(size_t)BATCH * NNODE * CDIM]; // 81.9 MB (A seg2)
// folded layer-1 weights, fp16, [K=768][N=256] row-major
__device__ __half g_W16[768 * 256];

// ---------------- dtype detection ---------------------------------------------------
// Node indices < 20000 -> int64 storage has zero high words everywhere.
__global__ void k_detect(const int* __restrict__ p32) {
    int t = threadIdx.x;
    if (p32[2 * t + 1] != 0) atomicOr(&g_hi_nonzero, 1);
}
__device__ __forceinline__ void load_edge(const int* __restrict__ p, int e, int& s, int& d) {
    if (g_hi_nonzero) { s = p[e];      d = p[NEDGE + e]; }
    else              { s = p[2 * e];  d = p[2 * (NEDGE + e)]; }
}

// ---------------- graph prep kernels ------------------------------------------------
__global__ void k_zero() {
    int i = blockIdx.x * blockDim.x + threadIdx.x;
    if (i < NNODE) { g_deg[i] = 0; g_cnt[i] = 0; g_cursor[i] = 0; }
    if (i == 0) g_hi_nonzero = 0;
}
__global__ void k_deg(const int* __restrict__ ei) {
    int e = blockIdx.x * blockDim.x + threadIdx.x;
    if (e < NEDGE) {
        int s, d; load_edge(ei, e, s, d);
        atomicAdd(&g_deg[s], 1);
        atomicAdd(&g_cnt[d], 1);
    }
}
__global__ void k_dis() {
    int i = blockIdx.x * blockDim.x + threadIdx.x;
    if (i < NNODE) {
        int d = g_deg[i];
        g_dis[i] = (d > 0) ? rsqrtf((float)d) : 0.0f;
    }
}
__global__ void k_scan() {
    __shared__ int sh[1024];
    const int CH = 20;
    int t = threadIdx.x;
    int base = t * CH;
    int sum = 0;
    for (int i = 0; i < CH; i++) { int idx = base + i; if (idx < NNODE) sum += g_cnt[idx]; }
    sh[t] = sum;
    __syncthreads();
    for (int o = 1; o < 1024; o <<= 1) {
        int v = (t >= o) ? sh[t - o] : 0;
        __syncthreads();
        sh[t] += v;
        __syncthreads();
    }
    int run = sh[t] - sum;
    for (int i = 0; i < CH; i++) {
        int idx = base + i;
        if (idx < NNODE) { g_rowptr[idx] = run; run += g_cnt[idx]; }
    }
    if (t == 1023) g_rowptr[NNODE] = sh[1023];
}
__global__ void k_fill(const int* __restrict__ ei) {
    int e = blockIdx.x * blockDim.x + threadIdx.x;
    if (e < NEDGE) {
        int s, d; load_edge(ei, e, s, d);
        float w = -g_dis[s] * g_dis[d];
        int pos = atomicAdd(&g_cursor[d], 1);
        int idx = g_rowptr[d] + pos;
        g_csr_src[idx] = s;
        g_csr_w[idx]   = w;
    }
}

// convert feats fp32 -> fp16 plane
__global__ void k_half(const float* __restrict__ f) {
    size_t i = (size_t)blockIdx.x * blockDim.x + threadIdx.x;   // over elems/4
    float4 x = ((const float4*)f)[i];
    __half2 a = __floats2half2_rn(x.x, x.y);
    __half2 b = __floats2half2_rn(x.z, x.w);
    uint2 p;
    p.x = *(uint32_t*)&a;
    p.y = *(uint32_t*)&b;
    ((uint2*)g_feats16)[i] = p;
}

// fold layer-1 weights into fp16, [K=768][N=256]:
// Wc = [W0-W2 ; W1 ; 2*W2]  (since Tx2 = 2*P2 - Tx0)
__global__ void k_wc(const float* __restrict__ W) {
    int idx = blockIdx.x * blockDim.x + threadIdx.x;   // < 3*256*256, = kg*256 + n
    const int CC = CDIM * CDIM;
    int seg = idx / CC;
    int r   = idx - seg * CC;
    const float* Wl = W + 1 * 3 * CC;  // layer 1
    float v;
    if      (seg == 0) v = Wl[r] - Wl[2 * CC + r];
    else if (seg == 1) v = Wl[CC + r];
    else               v = 2.0f * Wl[2 * CC + r];
    g_W16[idx] = __float2half_rn(v);
}

// ---------------- propagation: Y[b,v,:] = sum_e norm[e] * X[b,src[e],:] ------------
// Warp-per-node, barrier-free, fp16 in/out with fp32 accumulate.
// phase 0: g_feats16 -> g_Tx116.  phase 1: g_Tx116 -> g_P216.
__global__ void __launch_bounds__(256, 8)
k_prop(int phase) {
    const __half* X16 = (phase == 0) ? g_feats16 : g_Tx116;
    __half*       Y16 = (phase == 0) ? g_Tx116 : g_P216;

    int wid  = threadIdx.x >> 5;
    int lane = threadIdx.x & 31;
    int v    = blockIdx.x * 8 + wid;
    int b    = blockIdx.y;

    int start = g_rowptr[v];
    int end   = g_rowptr[v + 1];

    const uint4* X = (const uint4*)(X16 + (size_t)b * NNODE * CDIM);

    float acc[8];
    #pragma unroll
    for (int j = 0; j < 8; j++) acc[j] = 0.0f;

    #pragma unroll 4
    for (int e = start; e < end; e++) {
        int   s = __ldg(&g_csr_src[e]);
        float w = __ldg(&g_csr_w[e]);
        uint4 raw = X[(size_t)s * 32 + lane];
        float2 f0 = __half22float2(*(__half2*)&raw.x);
        float2 f1 = __half22float2(*(__half2*)&raw.y);
        float2 f2 = __half22float2(*(__half2*)&raw.z);
        float2 f3 = __half22float2(*(__half2*)&raw.w);
        acc[0] += w * f0.x; acc[1] += w * f0.y;
        acc[2] += w * f1.x; acc[3] += w * f1.y;
        acc[4] += w * f2.x; acc[5] += w * f2.y;
        acc[6] += w * f3.x; acc[7] += w * f3.y;
    }

    __half2 o0 = __floats2half2_rn(acc[0], acc[1]);
    __half2 o1 = __floats2half2_rn(acc[2], acc[3]);
    __half2 o2 = __floats2half2_rn(acc[4], acc[5]);
    __half2 o3 = __floats2half2_rn(acc[6], acc[7]);
    uint4 p;
    p.x = *(uint32_t*)&o0; p.y = *(uint32_t*)&o1;
    p.z = *(uint32_t*)&o2; p.w = *(uint32_t*)&o3;
    ((uint4*)(Y16 + (size_t)b * NNODE * CDIM))[(size_t)v * 32 + lane] = p;
}

// ---------------- mma.sync helpers ----------------------------------------------------
__device__ __forceinline__ uint32_t smem_u32(const void* p) {
    uint32_t a;
    asm("{ .reg .u64 t; cvta.to.shared.u64 t, %1; cvt.u32.u64 %0, t; }" : "=r"(a) : "l"(p));
    return a;
}
__device__ __forceinline__ void ldsm_x4(uint32_t& r0, uint32_t& r1, uint32_t& r2, uint32_t& r3,
                                        uint32_t addr) {
    asm volatile("ldmatrix.sync.aligned.m8n8.x4.shared.b16 {%0,%1,%2,%3}, [%4];"
                 : "=r"(r0), "=r"(r1), "=r"(r2), "=r"(r3) : "r"(addr));
}
__device__ __forceinline__ void ldsm_x4t(uint32_t& r0, uint32_t& r1, uint32_t& r2, uint32_t& r3,
                                         uint32_t addr) {
    asm volatile("ldmatrix.sync.aligned.m8n8.x4.trans.shared.b16 {%0,%1,%2,%3}, [%4];"
                 : "=r"(r0), "=r"(r1), "=r"(r2), "=r"(r3) : "r"(addr));
}
__device__ __forceinline__ void mma_f16(float* c, const uint32_t* a, uint32_t b0, uint32_t b1) {
    asm volatile("mma.sync.aligned.m16n8k16.row.col.f32.f16.f16.f32 "
                 "{%0,%1,%2,%3}, {%4,%5,%6,%7}, {%8,%9}, {%0,%1,%2,%3};"
                 : "+f"(c[0]), "+f"(c[1]), "+f"(c[2]), "+f"(c[3])
                 : "r"(a[0]), "r"(a[1]), "r"(a[2]), "r"(a[3]), "r"(b0), "r"(b1));
}
__device__ __forceinline__ void cp16(uint32_t dst, const void* src) {
    asm volatile("{ .reg .u64 g; cvta.to.global.u64 g, %1;\n\t"
                 "cp.async.ca.shared.global [%0], [g], 16; }" :: "r"(dst), "l"(src));
}

// ---------------- GEMM (mma.sync fp16) + bias + LayerNorm ----------------------------
// out[160000,256] = [Tx0|Tx1|P2]_fp16 (M x 768) @ W16 + b, then row LN.
// CTA: M=64, N=256, BK=32. 8 warps = 2(M) x 4(N); warp tile 32 x 64.  (R12 shape)
// B fragments loaded via ldmatrix.x4.trans (one instr covers two nt tiles):
// per k-step LDSM count drops 10 -> 6 for the same 16 HMMA.
#define A_ROWB  80                     // 32 fp16 = 64B + 16B pad
#define A_STG   (64 * A_ROWB)          // 5120
#define B_ROWB  528                    // 256 fp16 = 512B + 16B pad
#define B_STG   (32 * B_ROWB)          // 16896
#define OFF_A(s) ((s) * A_STG)                 // 0 / 5120
#define OFF_B(s) (2 * A_STG + (s) * B_STG)     // 10240 / 27136
#define SMEM_DYN 65536                 // also fits the [64][256] f32 epilogue

__global__ void __launch_bounds__(256, 2)
k_gemm_mma(const float* __restrict__ bias,
           const float* __restrict__ lnw,
           const float* __restrict__ lnb,
           float* __restrict__ out)
{
    extern __shared__ char smem[];
    const uint32_t sb = smem_u32(smem);
    const int tid  = threadIdx.x;
    const int wid  = tid >> 5;
    const int lane = tid & 31;
    const int wm   = wid >> 2;          // 0..1 (M)
    const int wn   = wid & 3;           // 0..3 (N)
    const int m0   = blockIdx.x * 64;

    float acc[2][8][4];
    #pragma unroll
    for (int mt = 0; mt < 2; mt++)
        #pragma unroll
        for (int nt = 0; nt < 8; nt++)
            #pragma unroll
            for (int q = 0; q < 4; q++) acc[mt][nt][q] = 0.0f;

    // A: 256 x 16B chunks cover [64][32] fp16; thread t -> row=t>>2, q=t&3
    const int arow = tid >> 2;
    const int aq   = tid & 3;

    // B ldsm.x4.trans lane addressing (two adjacent nt tiles per instruction):
    //   group g = lane>>3: g0: k rows 0-7 @ ncol; g1: k rows 8-15 @ ncol;
    //   g2: k rows 0-7 @ ncol+8; g3: k rows 8-15 @ ncol+8.
    const uint32_t bg   = lane >> 3;
    const uint32_t brow = (lane & 7) + ((bg & 1) << 3);   // k-row offset 0..15
    const uint32_t bcol = (bg & 2) << 2;                  // +0 or +8 columns

    // prefetch helper: A chunk + B chunk -> one cp.async group
    auto prefetch = [&](int c, int s) {
        int seg  = c >> 3;
        const __half* Aseg = (seg == 0) ? g_feats16 : (seg == 1) ? g_Tx116 : g_P216;
        int koff = (c & 7) * 32;
        cp16(sb + OFF_A(s) + arow * A_ROWB + aq * 16,
             Aseg + (size_t)(m0 + arow) * CDIM + koff + aq * 8);
        int kb = c * 32;
        #pragma unroll
        for (int i = 0; i < 4; i++) {
            int idx = tid + 256 * i;       // 0..1023
            int row = idx >> 5;            // 0..31
            int q   = idx & 31;            // 16B chunk in 512B row
            cp16(sb + OFF_B(s) + row * B_ROWB + q * 16,
                 g_W16 + (size_t)(kb + row) * 256 + q * 8);
        }
        asm volatile("cp.async.commit_group;" ::: "memory");
    };

    prefetch(0, 0);

    for (int c = 0; c < 24; c++) {
        const int s = c & 1;

        __syncthreads();                   // reads of stage s^1 (prev compute) done
        if (c + 1 < 24) {
            prefetch(c + 1, s ^ 1);
            asm volatile("cp.async.wait_group 1;" ::: "memory");   // chunk c ready
        } else {
            asm volatile("cp.async.wait_group 0;" ::: "memory");
        }
        __syncthreads();                   // stage s visible to all

        #pragma unroll
        for (int k = 0; k < 2; k++) {
            uint32_t af[2][4];
            #pragma unroll
            for (int mt = 0; mt < 2; mt++) {
                uint32_t ar = (uint32_t)(wm * 32 + mt * 16 + (lane & 15));
                uint32_t aoff = OFF_A(s) + ar * A_ROWB + (uint32_t)(k * 32 + (lane >> 4) * 16);
                ldsm_x4(af[mt][0], af[mt][1], af[mt][2], af[mt][3], sb + aoff);
            }
            #pragma unroll
            for (int nt2 = 0; nt2 < 4; nt2++) {        // pairs of nt tiles
                uint32_t boff = OFF_B(s) + (uint32_t)(k * 16 + brow) * B_ROWB
                              + (uint32_t)(wn * 64 + nt2 * 16 + bcol) * 2;
                uint32_t b0, b1, b2, b3;
                ldsm_x4t(b0, b1, b2, b3, sb + boff);
                #pragma unroll
                for (int mt = 0; mt < 2; mt++) {
                    mma_f16(acc[mt][nt2 * 2 + 0], af[mt], b0, b1);
                    mma_f16(acc[mt][nt2 * 2 + 1], af[mt], b2, b3);
                }
            }
        }
    }

    // ---- epilogue: acc -> SMEM, then LN per row ----
    __syncthreads();
    float* ep = (float*)smem;                 // [64][256] f32 = 64KB (aliases all bufs)
    #pragma unroll
    for (int mt = 0; mt < 2; mt++) {
        int r0 = wm * 32 + mt * 16 + (lane >> 2);
        #pragma unroll
        for (int nt = 0; nt < 8; nt++) {
            int cbase = wn * 64 + nt * 8 + (lane & 3) * 2;
            *(float2*)(ep + r0 * 256 + cbase)       = make_float2(acc[mt][nt][0], acc[mt][nt][1]);
            *(float2*)(ep + (r0 + 8) * 256 + cbase) = make_float2(acc[mt][nt][2], acc[mt][nt][3]);
        }
    }
    __syncthreads();

    // warp wid handles rows wid*8..+8; lane covers cols {j*32+lane}
    float bb[8], lw[8], lb[8];
    #pragma unroll
    for (int j = 0; j < 8; j++) {
        int col = j * 32 + lane;
        bb[j] = bias[col]; lw[j] = lnw[col]; lb[j] = lnb[col];
    }
    #pragma unroll
    for (int i = 0; i < 8; i++) {
        int row = wid * 8 + i;
        float v[8];
        float ssum = 0.0f;
        #pragma unroll
        for (int j = 0; j < 8; j++) {
            v[j] = ep[row * 256 + j * 32 + lane] + bb[j];
            ssum += v[j];
        }
        #pragma unroll
        for (int o = 16; o > 0; o >>= 1) ssum += __shfl_xor_sync(0xffffffffu, ssum, o);
        float mu = ssum * (1.0f / CDIM);
        float s2 = 0.0f;
        #pragma unroll
        for (int j = 0; j < 8; j++) { float d = v[j] - mu; s2 += d * d; }
        #pragma unroll
        for (int o = 16; o > 0; o >>= 1) s2 += __shfl_xor_sync(0xffffffffu, s2, o);
        float inv = rsqrtf(s2 * (1.0f / CDIM) + 1e-5f);

        size_t rbase = ((size_t)m0 + row) * CDIM;
        #pragma unroll
        for (int j = 0; j < 8; j++)
            out[rbase + j * 32 + lane] = (v[j] - mu) * inv * lw[j] + lb[j];
    }
}

// ---------------- launch -------------------------------------------------------------
extern "C" void kernel_launch(void* const* d_in, const int* in_sizes, int n_in,
                              void* d_out, int out_size) {
    const float* feats = (const float*)d_in[0];      // [B*N, C]
    const float* W     = (const float*)d_in[1];      // [L,K,C,C]
    const float* bpar  = (const float*)d_in[2];      // [L,C]
    const float* lnw   = (const float*)d_in[3];      // [L,C]
    const float* lnb   = (const float*)d_in[4];      // [L,C]
    const int*   ei    = (const int*)d_in[5];        // [2,E] int32 OR int64 (detected)
    float* out = (float*)d_out;

    cudaFuncSetAttribute(k_gemm_mma, cudaFuncAttributeMaxDynamicSharedMemorySize, SMEM_DYN);

    k_zero  <<<(NNODE + 255) / 256, 256>>>();
    k_detect<<<1, 256>>>(ei);
    k_deg   <<<(NEDGE + 255) / 256, 256>>>(ei);
    k_dis   <<<(NNODE + 255) / 256, 256>>>();
    k_scan  <<<1, 1024>>>();
    k_fill  <<<(NEDGE + 255) / 256, 256>>>(ei);
    k_wc    <<<(3 * CDIM * CDIM) / 256, 256>>>(W);
    k_half  <<<(BATCH * NNODE * CDIM / 4) / 256, 256>>>(feats);

    k_prop<<<dim3(NNODE / 8, BATCH), 256>>>(0);   // Tx1 = A_hat @ feats
    k_prop<<<dim3(NNODE / 8, BATCH), 256>>>(1);   // P2  = A_hat @ Tx1

    // only layer 1 survives in the reference -> use its params
    k_gemm_mma<<<(BATCH * NNODE) / 64, 256, SMEM_DYN>>>(
        bpar + CDIM, lnw + CDIM, lnb + CDIM, out);
}